// round 1
// baseline (speedup 1.0000x reference)
#include <cuda_runtime.h>
#include <math.h>

// Problem dims
#define NB   4
#define NS   896
#define ND   1024
#define NH   16
#define NDH  64
#define NI   4096
#define NOUT 4096
#define NL   2
#define NM   128
#define NT   1024          // NM + NS
#define NBT  4096          // NB * NT

// ---------------- scratch (device globals; no allocation allowed) ----------------
__device__ float g_x[NBT * ND];                         // running activations [B,T,D]
__device__ float g_q[NBT * ND];                         // Q / generic temp
__device__ float g_k[NBT * ND];
__device__ float g_v[NBT * ND];
__device__ float g_t0[NBT * ND];                        // attention output
__device__ float g_inter[(size_t)NBT * NI];             // FFN intermediate
__device__ float g_scores[(size_t)NB * NH * NT * NT];   // attention scores

__device__ __forceinline__ float gelu_f(float x) {
    return 0.5f * x * (1.0f + erff(x * 0.7071067811865476f));
}

// ---------------- generic batched GEMM ----------------
// C[z] = act(alpha * A[z] @ B[z] + bias)
// A: [M,K] row-major (lda), B: [K,N] (ldb) or [N,K] if TRANSB, C: [M,N] (ldc)
// Per-batch offsets: off = (z/h)*outer + (z%h)*inner  for each operand.
// Grid covers M,N exactly (all dims divisible by tiles) -> no bounds checks.
template<int BM, int BN, int BK, int TM, int TN, bool TRANSB, int ACT>
__global__ void __launch_bounds__(256) gemm_kernel(
    const float* __restrict__ A, const float* __restrict__ Bm,
    const float* __restrict__ bias, float* __restrict__ C,
    int K, int lda, int ldb, int ldc,
    long long oA, long long iA, long long oB, long long iB,
    long long oC, long long iC, int h, float alpha)
{
    constexpr int THREADS = (BM / TM) * (BN / TN);
    __shared__ float As[BK][BM + 4];
    __shared__ float Bs[BK][BN + 4];

    const int z = blockIdx.z;
    A  += (long long)(z / h) * oA + (long long)(z % h) * iA;
    Bm += (long long)(z / h) * oB + (long long)(z % h) * iB;
    C  += (long long)(z / h) * oC + (long long)(z % h) * iC;

    const int bm = blockIdx.y * BM;
    const int bn = blockIdx.x * BN;
    const int tid = threadIdx.x;
    const int ty = tid / (BN / TN);
    const int tx = tid % (BN / TN);

    float acc[TM][TN];
#pragma unroll
    for (int i = 0; i < TM; i++)
#pragma unroll
        for (int j = 0; j < TN; j++) acc[i][j] = 0.0f;

    for (int k0 = 0; k0 < K; k0 += BK) {
#pragma unroll
        for (int idx = tid; idx < BM * BK; idx += THREADS) {
            int m = idx / BK, k = idx % BK;
            As[k][m] = A[(long long)(bm + m) * lda + (k0 + k)];
        }
        if (!TRANSB) {
#pragma unroll
            for (int idx = tid; idx < BK * BN; idx += THREADS) {
                int k = idx / BN, n = idx % BN;
                Bs[k][n] = Bm[(long long)(k0 + k) * ldb + (bn + n)];
            }
        } else {
#pragma unroll
            for (int idx = tid; idx < BK * BN; idx += THREADS) {
                int n = idx / BK, k = idx % BK;
                Bs[k][n] = Bm[(long long)(bn + n) * ldb + (k0 + k)];
            }
        }
        __syncthreads();

#pragma unroll
        for (int k = 0; k < BK; k++) {
            float a[TM], b[TN];
#pragma unroll
            for (int i = 0; i < TM; i += 4)
                *reinterpret_cast<float4*>(&a[i]) =
                    *reinterpret_cast<const float4*>(&As[k][ty * TM + i]);
#pragma unroll
            for (int j = 0; j < TN; j += 4)
                *reinterpret_cast<float4*>(&b[j]) =
                    *reinterpret_cast<const float4*>(&Bs[k][tx * TN + j]);
#pragma unroll
            for (int i = 0; i < TM; i++)
#pragma unroll
                for (int j = 0; j < TN; j++)
                    acc[i][j] = fmaf(a[i], b[j], acc[i][j]);
        }
        __syncthreads();
    }

#pragma unroll
    for (int i = 0; i < TM; i++) {
        const int m = bm + ty * TM + i;
#pragma unroll
        for (int j = 0; j < TN; j++) {
            const int n = bn + tx * TN + j;
            float v = acc[i][j] * alpha;
            if (bias) v += bias[n];
            if (ACT == 1) v = gelu_f(v);
            C[(long long)m * ldc + n] = v;
        }
    }
}

// ---------------- concat [mem_emb ; hidden_states] -> g_x ----------------
__global__ void concat_kernel(const float* __restrict__ hs, const float* __restrict__ mem) {
    int idx = blockIdx.x * blockDim.x + threadIdx.x;
    if (idx >= NBT * ND) return;
    int d = idx % ND;
    int t = (idx / ND) % NT;
    int b = idx / (ND * NT);
    g_x[idx] = (t < NM) ? mem[t * ND + d]
                        : hs[((size_t)(b * NS) + (t - NM)) * ND + d];
}

// ---------------- row softmax over g_scores (row length NT) ----------------
__global__ void __launch_bounds__(256) softmax_kernel() {
    float* row = g_scores + (size_t)blockIdx.x * NT;
    __shared__ float red[8];
    __shared__ float s_val;
    const int tid = threadIdx.x;
    float v[4];
#pragma unroll
    for (int i = 0; i < 4; i++) v[i] = row[tid + i * 256];
    float mx = fmaxf(fmaxf(v[0], v[1]), fmaxf(v[2], v[3]));
    for (int o = 16; o > 0; o >>= 1) mx = fmaxf(mx, __shfl_xor_sync(0xffffffffu, mx, o));
    if ((tid & 31) == 0) red[tid >> 5] = mx;
    __syncthreads();
    if (tid == 0) { float m = red[0]; for (int i = 1; i < 8; i++) m = fmaxf(m, red[i]); s_val = m; }
    __syncthreads();
    const float m = s_val;
    float s = 0.0f;
#pragma unroll
    for (int i = 0; i < 4; i++) { v[i] = expf(v[i] - m); s += v[i]; }
    for (int o = 16; o > 0; o >>= 1) s += __shfl_xor_sync(0xffffffffu, s, o);
    if ((tid & 31) == 0) red[tid >> 5] = s;
    __syncthreads();
    if (tid == 0) { float t = 0; for (int i = 0; i < 8; i++) t += red[i]; s_val = 1.0f / t; }
    __syncthreads();
    const float inv = s_val;
#pragma unroll
    for (int i = 0; i < 4; i++) row[tid + i * 256] = v[i] * inv;
}

// ---------------- x = LayerNorm(y + x) * g + b  (in place into g_x) ----------------
__global__ void __launch_bounds__(256) add_ln_kernel(
    const float* __restrict__ y, const float* __restrict__ g, const float* __restrict__ bt)
{
    __shared__ float red[8];
    __shared__ float s_mean, s_inv;
    const int tid = threadIdx.x;
    const size_t base = (size_t)blockIdx.x * ND;
    float v[4];
    float s = 0.0f;
#pragma unroll
    for (int i = 0; i < 4; i++) {
        int c = tid + i * 256;
        v[i] = y[base + c] + g_x[base + c];
        s += v[i];
    }
    for (int o = 16; o > 0; o >>= 1) s += __shfl_xor_sync(0xffffffffu, s, o);
    if ((tid & 31) == 0) red[tid >> 5] = s;
    __syncthreads();
    if (tid == 0) { float t = 0; for (int i = 0; i < 8; i++) t += red[i]; s_mean = t * (1.0f / ND); }
    __syncthreads();
    const float mean = s_mean;
    float vs = 0.0f;
#pragma unroll
    for (int i = 0; i < 4; i++) { float d = v[i] - mean; vs += d * d; }
    for (int o = 16; o > 0; o >>= 1) vs += __shfl_xor_sync(0xffffffffu, vs, o);
    if ((tid & 31) == 0) red[tid >> 5] = vs;
    __syncthreads();
    if (tid == 0) { float t = 0; for (int i = 0; i < 8; i++) t += red[i]; s_inv = rsqrtf(t * (1.0f / ND) + 1e-12f); }
    __syncthreads();
    const float inv = s_inv;
#pragma unroll
    for (int i = 0; i < 4; i++) {
        int c = tid + i * 256;
        g_x[base + c] = (v[i] - mean) * inv * g[c] + bt[c];
    }
}

// ---------------- read_out = x[:, :NM] ----------------
__global__ void readout_kernel(float* __restrict__ out) {
    int idx = blockIdx.x * blockDim.x + threadIdx.x;
    if (idx >= NB * NM * ND) return;
    int d = idx % ND;
    int t = (idx / ND) % NM;
    int b = idx / (ND * NM);
    out[(size_t)NB * NS * NOUT + idx] = g_x[((size_t)b * NT + t) * ND + d];
}

extern "C" void kernel_launch(void* const* d_in, const int* in_sizes, int n_in,
                              void* d_out, int out_size) {
    const float* hs   = (const float*)d_in[0];
    const float* mem  = (const float*)d_in[1];
    const float* Wq   = (const float*)d_in[2];
    const float* bq   = (const float*)d_in[3];
    const float* Wk   = (const float*)d_in[4];
    const float* bk   = (const float*)d_in[5];
    const float* Wv   = (const float*)d_in[6];
    const float* bv   = (const float*)d_in[7];
    const float* Wo   = (const float*)d_in[8];
    const float* bo   = (const float*)d_in[9];
    const float* ln1g = (const float*)d_in[10];
    const float* ln1b = (const float*)d_in[11];
    const float* Wm   = (const float*)d_in[12];
    const float* bm   = (const float*)d_in[13];
    const float* Wr   = (const float*)d_in[14];
    const float* br   = (const float*)d_in[15];
    const float* ln2g = (const float*)d_in[16];
    const float* ln2b = (const float*)d_in[17];
    const float* Wp   = (const float*)d_in[18];
    const float* bp   = (const float*)d_in[19];
    float* out = (float*)d_out;

    static float *p_x = nullptr, *p_q, *p_k, *p_v, *p_t0, *p_inter, *p_scores;
    if (!p_x) {
        cudaGetSymbolAddress((void**)&p_x,      g_x);
        cudaGetSymbolAddress((void**)&p_q,      g_q);
        cudaGetSymbolAddress((void**)&p_k,      g_k);
        cudaGetSymbolAddress((void**)&p_v,      g_v);
        cudaGetSymbolAddress((void**)&p_t0,     g_t0);
        cudaGetSymbolAddress((void**)&p_inter,  g_inter);
        cudaGetSymbolAddress((void**)&p_scores, g_scores);
    }

    const long long Z = 0;
    {
        int n = NBT * ND;
        concat_kernel<<<(n + 255) / 256, 256>>>(hs, mem);
    }

    for (int l = 0; l < NL; l++) {
        const float* wq = Wq + (size_t)l * ND * ND;
        const float* wk = Wk + (size_t)l * ND * ND;
        const float* wv = Wv + (size_t)l * ND * ND;
        const float* wo = Wo + (size_t)l * ND * ND;
        const float* wm = Wm + (size_t)l * ND * NI;
        const float* wr = Wr + (size_t)l * NI * ND;

        // Q, K, V projections: [4096,1024] = x @ W + b
        gemm_kernel<128,128,8,8,8,false,0><<<dim3(ND/128, NBT/128, 1), 256>>>(
            p_x, wq, bq + l*ND, p_q, ND, ND, ND, ND, Z,Z,Z,Z,Z,Z, 1, 1.0f);
        gemm_kernel<128,128,8,8,8,false,0><<<dim3(ND/128, NBT/128, 1), 256>>>(
            p_x, wk, bk + l*ND, p_k, ND, ND, ND, ND, Z,Z,Z,Z,Z,Z, 1, 1.0f);
        gemm_kernel<128,128,8,8,8,false,0><<<dim3(ND/128, NBT/128, 1), 256>>>(
            p_x, wv, bv + l*ND, p_v, ND, ND, ND, ND, Z,Z,Z,Z,Z,Z, 1, 1.0f);

        // scores[b,h] = Q[b,h] @ K[b,h]^T / 8   (batched, TRANSB)
        gemm_kernel<128,128,8,8,8,true,0><<<dim3(NT/128, NT/128, NB*NH), 256>>>(
            p_q, p_k, nullptr, p_scores, NDH, ND, ND, NT,
            (long long)NT*ND, (long long)NDH,
            (long long)NT*ND, (long long)NDH,
            (long long)NH*NT*NT, (long long)NT*NT, NH, 0.125f);

        softmax_kernel<<<NB*NH*NT, 256>>>();

        // attn_out[b,h] = P[b,h] @ V[b,h]   (batched, N=64)
        gemm_kernel<64,64,8,4,4,false,0><<<dim3(1, NT/64, NB*NH), 256>>>(
            p_scores, p_v, nullptr, p_t0, NT, NT, ND, ND,
            (long long)NH*NT*NT, (long long)NT*NT,
            (long long)NT*ND, (long long)NDH,
            (long long)NT*ND, (long long)NDH, NH, 1.0f);

        // O projection
        gemm_kernel<128,128,8,8,8,false,0><<<dim3(ND/128, NBT/128, 1), 256>>>(
            p_t0, wo, bo + l*ND, p_q, ND, ND, ND, ND, Z,Z,Z,Z,Z,Z, 1, 1.0f);
        add_ln_kernel<<<NBT, 256>>>(p_q, ln1g + l*ND, ln1b + l*ND);

        // FFN up + GELU
        gemm_kernel<128,128,8,8,8,false,1><<<dim3(NI/128, NBT/128, 1), 256>>>(
            p_x, wm, bm + l*NI, p_inter, ND, ND, NI, NI, Z,Z,Z,Z,Z,Z, 1, 1.0f);
        // FFN down
        gemm_kernel<128,128,8,8,8,false,0><<<dim3(ND/128, NBT/128, 1), 256>>>(
            p_inter, wr, br + l*ND, p_q, NI, NI, ND, ND, Z,Z,Z,Z,Z,Z, 1, 1.0f);
        add_ln_kernel<<<NBT, 256>>>(p_q, ln2g + l*ND, ln2b + l*ND);
    }

    // out = gelu(x[:, NM:] @ Wp + bp)  (batched over B, rows offset by NM)
    gemm_kernel<128,128,8,8,8,false,1><<<dim3(NOUT/128, NS/128, NB), 256>>>(
        p_x + (size_t)NM*ND, Wp, bp, out, ND, ND, NOUT, NOUT,
        (long long)NT*ND, Z, Z, Z, (long long)NS*NOUT, Z, 1, 1.0f);

    {
        int n = NB * NM * ND;
        readout_kernel<<<(n + 255) / 256, 256>>>(out);
    }
}